// round 5
// baseline (speedup 1.0000x reference)
#include <cuda_runtime.h>
#include <cuda_fp16.h>
#include <mma.h>

using namespace nvcuda;

#define N_CELLS 8192
#define D_GENE  1024
#define D_EMB   256
#define KCAT    768   // [hi | lo | hi] split concat along K

// ---------------- scratch (device globals; no allocation allowed) ----------------
__device__ __half g_Bcat[(size_t)N_CELLS * KCAT];   // [Eh | Eh | El]   12.6 MB
__device__ __half g_Acat[(size_t)N_CELLS * KCAT];   // [Ph | Pl | Ph]   12.6 MB
__device__ __half g_B2[(size_t)KCAT * D_EMB];       // [Th ; Tl ; Th]    0.4 MB
__device__ __half g_Xh[(size_t)N_CELLS * D_GENE];   // expression fp16  16 MB
__device__ __half g_Gh[(size_t)D_GENE * D_GENE];    // gene_response    2 MB
__device__ __half g_gated[(size_t)N_CELLS * N_CELLS]; // gated matrix  128 MB
__device__ __half g_M1h[(size_t)N_CELLS * D_GENE];  // (gated@expr)     16 MB

// ---------------- conversion kernels (identical to round-1 pass) ----------------
__global__ void k_cvt_expr(const float* __restrict__ in) {
    int i = blockIdx.x * blockDim.x + threadIdx.x;
    if (i < N_CELLS * D_GENE) g_Xh[i] = __float2half_rn(in[i]);
}

__global__ void k_cvt_gr(const float* __restrict__ in) {
    int i = blockIdx.x * blockDim.x + threadIdx.x;
    if (i < D_GENE * D_GENE) g_Gh[i] = __float2half_rn(in[i]);
}

// encoding [N, 256] -> Bcat [N, 768] = [Eh | Eh | El]
__global__ void k_cvt_enc(const float* __restrict__ enc) {
    int i = blockIdx.x * blockDim.x + threadIdx.x;
    if (i >= N_CELLS * D_EMB) return;
    int m = i / D_EMB, c = i % D_EMB;
    float x = enc[i];
    __half h = __float2half_rn(x);
    __half l = __float2half_rn(x - __half2float(h));
    size_t base = (size_t)m * KCAT + c;
    g_Bcat[base]             = h;
    g_Bcat[base + D_EMB]     = h;
    g_Bcat[base + 2 * D_EMB] = l;
}

// transform [256, 256] -> B2 [768, 256] = [Th ; Tl ; Th]
__global__ void k_cvt_T(const float* __restrict__ T) {
    int i = blockIdx.x * blockDim.x + threadIdx.x;
    if (i >= D_EMB * D_EMB) return;
    int k = i / D_EMB, j = i % D_EMB;
    float x = T[i];
    __half h = __float2half_rn(x);
    __half l = __float2half_rn(x - __half2float(h));
    g_B2[(size_t)k * D_EMB + j]               = h;
    g_B2[(size_t)(k + D_EMB) * D_EMB + j]     = l;
    g_B2[(size_t)(k + 2 * D_EMB) * D_EMB + j] = h;
}

// ---------------- fused wmma GEMM (round-1 core + reg-buffered double buffer) ----
// MODE 0: P = Bcat @ B2         (M=8192, N=256,  K=768)  epi: split-write Acat
// MODE 1: S = Acat @ Bcat^T     (M=8192, N=8192, K=768)  epi: sigmoid * spatial -> gated
// MODE 2: M1 = gated @ Xh       (M=8192, N=1024, K=8192) epi: fp16 -> M1h
// MODE 3: out = M1h @ Gh        (M=8192, N=1024, K=1024) epi: *1/1024 -> out fp32
template <int MODE>
__global__ __launch_bounds__(256, 2)
void gemm_wmma(const float* __restrict__ aux, float* __restrict__ outf) {
    constexpr bool B_COL = (MODE == 1);
    constexpr int K    = (MODE <= 1) ? KCAT : (MODE == 2 ? N_CELLS : D_GENE);
    constexpr int Ndim = (MODE == 0) ? D_EMB : (MODE == 1 ? N_CELLS : D_GENE);

    const __half* __restrict__ A =
        (MODE == 0) ? g_Bcat : (MODE == 1) ? g_Acat : (MODE == 2) ? g_gated : g_M1h;
    const __half* __restrict__ B =
        (MODE == 0) ? g_B2 : (MODE == 1) ? g_Bcat : (MODE == 2) ? g_Xh : g_Gh;

    // double-buffered tiles; epilogue staging aliases Bs[0] after the main loop
    __shared__ __align__(16) __half As[2][128 * 40];   // 2 x 10240 B
    __shared__ __align__(16) __half Bs[2][128 * 40];   // 2 x 10240 B (row path uses [32][136] region)

    const int tid  = threadIdx.x;
    const int w    = tid >> 5;
    const int lane = tid & 31;
    const int wm   = w >> 2;   // 0..1
    const int wn   = w & 3;    // 0..3
    const size_t gm0 = (size_t)blockIdx.y * 128;
    const size_t gn0 = (size_t)blockIdx.x * 128;

    wmma::fragment<wmma::accumulator, 16, 16, 16, float> c[4][2];
#pragma unroll
    for (int i = 0; i < 4; i++)
#pragma unroll
        for (int j = 0; j < 2; j++) wmma::fill_fragment(c[i][j], 0.0f);

    // ---- register prefetch buffers ----
    float4 rA[2], rB[2];

    auto fetchA = [&](int k0) {
#pragma unroll
        for (int t = 0; t < 2; t++) {
            int idx = tid + t * 256;
            int row = idx >> 2, c4 = idx & 3;
            rA[t] = *(const float4*)(A + (gm0 + row) * K + k0 + c4 * 8);
        }
    };
    auto fetchB = [&](int k0) {
        if (B_COL) {
#pragma unroll
            for (int t = 0; t < 2; t++) {
                int idx = tid + t * 256;
                int row = idx >> 2, c4 = idx & 3;
                rB[t] = *(const float4*)(B + (gn0 + row) * K + k0 + c4 * 8);
            }
        } else {
#pragma unroll
            for (int t = 0; t < 2; t++) {
                int idx = tid + t * 256;
                int row = idx >> 4, c4 = idx & 15;
                rB[t] = *(const float4*)(B + (size_t)(k0 + row) * Ndim + gn0 + c4 * 8);
            }
        }
    };
    auto storeAB = [&](int buf) {
#pragma unroll
        for (int t = 0; t < 2; t++) {
            int idx = tid + t * 256;
            int row = idx >> 2, c4 = idx & 3;
            *(float4*)(&As[buf][row * 40 + c4 * 8]) = rA[t];
        }
        if (B_COL) {
#pragma unroll
            for (int t = 0; t < 2; t++) {
                int idx = tid + t * 256;
                int row = idx >> 2, c4 = idx & 3;
                *(float4*)(&Bs[buf][row * 40 + c4 * 8]) = rB[t];
            }
        } else {
#pragma unroll
            for (int t = 0; t < 2; t++) {
                int idx = tid + t * 256;
                int row = idx >> 4, c4 = idx & 15;
                *(float4*)(&Bs[buf][row * 136 + c4 * 8]) = rB[t];
            }
        }
    };

    fetchA(0);
    fetchB(0);

#pragma unroll 1
    for (int k0 = 0; k0 < K; k0 += 32) {
        const int buf = (k0 >> 5) & 1;
        storeAB(buf);
        __syncthreads();   // orders store(buf) after compute(buf) of two iters ago,
                           // and makes this iter's tiles visible to all warps
        if (k0 + 32 < K) { fetchA(k0 + 32); fetchB(k0 + 32); }  // overlap with compute

#pragma unroll
        for (int kk = 0; kk < 32; kk += 16) {
            if constexpr (B_COL) {
                wmma::fragment<wmma::matrix_b, 16, 16, 16, __half, wmma::col_major> b[2];
                wmma::load_matrix_sync(b[0], &Bs[buf][(wn * 32 + 0)  * 40 + kk], 40);
                wmma::load_matrix_sync(b[1], &Bs[buf][(wn * 32 + 16) * 40 + kk], 40);
#pragma unroll
                for (int i = 0; i < 4; i++) {
                    wmma::fragment<wmma::matrix_a, 16, 16, 16, __half, wmma::row_major> a;
                    wmma::load_matrix_sync(a, &As[buf][(wm * 64 + i * 16) * 40 + kk], 40);
                    wmma::mma_sync(c[i][0], a, b[0], c[i][0]);
                    wmma::mma_sync(c[i][1], a, b[1], c[i][1]);
                }
            } else {
                wmma::fragment<wmma::matrix_b, 16, 16, 16, __half, wmma::row_major> b[2];
                wmma::load_matrix_sync(b[0], &Bs[buf][kk * 136 + wn * 32 + 0],  136);
                wmma::load_matrix_sync(b[1], &Bs[buf][kk * 136 + wn * 32 + 16], 136);
#pragma unroll
                for (int i = 0; i < 4; i++) {
                    wmma::fragment<wmma::matrix_a, 16, 16, 16, __half, wmma::row_major> a;
                    wmma::load_matrix_sync(a, &As[buf][(wm * 64 + i * 16) * 40 + kk], 40);
                    wmma::mma_sync(c[i][0], a, b[0], c[i][0]);
                    wmma::mma_sync(c[i][1], a, b[1], c[i][1]);
                }
            }
        }
    }

    // ---------------- epilogue (round-1 proven path; epbuf aliases Bs[0]) ----------
    __syncthreads();   // all compute done before reusing Bs[0] as staging
    float* epbuf = ((float*)&Bs[0][0]) + w * 320;   // 16x20 per warp

    const int r     = lane >> 1;
    const int cbase = (lane & 1) * 8;
#pragma unroll
    for (int i = 0; i < 4; i++) {
#pragma unroll
        for (int j = 0; j < 2; j++) {
            wmma::store_matrix_sync(epbuf, c[i][j], 20, wmma::mem_row_major);
            __syncwarp();
            size_t gr = gm0 + wm * 64 + i * 16 + r;
            size_t gc = gn0 + wn * 32 + j * 16 + cbase;
#pragma unroll
            for (int e = 0; e < 8; e++) {
                float v = epbuf[r * 20 + cbase + e];
                size_t col = gc + e;
                if constexpr (MODE == 0) {
                    __half h = __float2half_rn(v);
                    __half l = __float2half_rn(v - __half2float(h));
                    size_t base = gr * KCAT + col;
                    g_Acat[base]             = h;   // Ph
                    g_Acat[base + D_EMB]     = l;   // Pl
                    g_Acat[base + 2 * D_EMB] = h;   // Ph
                } else if constexpr (MODE == 1) {
                    size_t idx = gr * (size_t)N_CELLS + col;
                    float pdv = aux[idx];
                    float sig = 1.0f / (1.0f + __expf(-v));
                    g_gated[idx] = __float2half_rn(sig * __expf(pdv * -1e-4f));
                } else if constexpr (MODE == 2) {
                    g_M1h[gr * D_GENE + col] = __float2half_rn(v);
                } else {
                    outf[gr * D_GENE + col] = v * (1.0f / 1024.0f);
                }
            }
            __syncwarp();
        }
    }
}

// ---------------- launch ----------------
extern "C" void kernel_launch(void* const* d_in, const int* in_sizes, int n_in,
                              void* d_out, int out_size) {
    const float* expr = (const float*)d_in[0];
    const float* enc  = (const float*)d_in[1];
    const float* pd   = (const float*)d_in[2];
    const float* T    = (const float*)d_in[3];
    const float* gr   = (const float*)d_in[4];
    float* out = (float*)d_out;

    k_cvt_expr<<<(N_CELLS * D_GENE) / 256, 256>>>(expr);
    k_cvt_gr<<<(D_GENE * D_GENE) / 256, 256>>>(gr);
    k_cvt_enc<<<(N_CELLS * D_EMB) / 256, 256>>>(enc);
    k_cvt_T<<<(D_EMB * D_EMB) / 256, 256>>>(T);

    // P = enc @ T (fp16 hi/lo split, K=768), split-write into Acat
    gemm_wmma<0><<<dim3(D_EMB / 128, N_CELLS / 128), 256>>>(nullptr, nullptr);
    // scores + sigmoid + spatial gate -> gated (fp16)
    gemm_wmma<1><<<dim3(N_CELLS / 128, N_CELLS / 128), 256>>>(pd, nullptr);
    // M1 = gated @ expression -> fp16
    gemm_wmma<2><<<dim3(D_GENE / 128, N_CELLS / 128), 256>>>(nullptr, nullptr);
    // out = M1 @ gene_response / 1024 -> fp32
    gemm_wmma<3><<<dim3(D_GENE / 128, N_CELLS / 128), 256>>>(nullptr, out);
}

// round 7
// speedup vs baseline: 1.0260x; 1.0260x over previous
#include <cuda_runtime.h>
#include <cuda_fp16.h>
#include <mma.h>
#include <cstdint>

using namespace nvcuda;

#define N_CELLS 8192
#define D_GENE  1024
#define D_EMB   256
#define KCAT    768   // [hi | lo | hi] split concat along K

// ---------------- scratch (device globals; no allocation allowed) ----------------
__device__ __half g_Bcat[(size_t)N_CELLS * KCAT];   // [Eh | Eh | El]   [N,K]
__device__ __half g_Acat[(size_t)N_CELLS * KCAT];   // [Ph | Pl | Ph]   [M,K]
__device__ __half g_B2[(size_t)KCAT * D_EMB];       // [Th ; Tl ; Th]   [K,N]
__device__ __half g_Xh[(size_t)N_CELLS * D_GENE];   // expression fp16  [K,N]
__device__ __half g_Gh[(size_t)D_GENE * D_GENE];    // gene_response    [K,N]
__device__ __half g_gated[(size_t)N_CELLS * N_CELLS]; // gated matrix   128 MB
__device__ __half g_M1h[(size_t)N_CELLS * D_GENE];  // (gated@expr)

// ---------------- conversion kernels (R1 originals, proven) ----------------
__global__ void k_cvt_expr(const float* __restrict__ in) {
    int i = blockIdx.x * blockDim.x + threadIdx.x;
    if (i < N_CELLS * D_GENE) g_Xh[i] = __float2half_rn(in[i]);
}

__global__ void k_cvt_gr(const float* __restrict__ in) {
    int i = blockIdx.x * blockDim.x + threadIdx.x;
    if (i < D_GENE * D_GENE) g_Gh[i] = __float2half_rn(in[i]);
}

__global__ void k_cvt_enc(const float* __restrict__ enc) {
    int i = blockIdx.x * blockDim.x + threadIdx.x;
    if (i >= N_CELLS * D_EMB) return;
    int m = i / D_EMB, c = i % D_EMB;
    float x = enc[i];
    __half h = __float2half_rn(x);
    __half l = __float2half_rn(x - __half2float(h));
    size_t base = (size_t)m * KCAT + c;
    g_Bcat[base]             = h;
    g_Bcat[base + D_EMB]     = h;
    g_Bcat[base + 2 * D_EMB] = l;
}

__global__ void k_cvt_T(const float* __restrict__ T) {
    int i = blockIdx.x * blockDim.x + threadIdx.x;
    if (i >= D_EMB * D_EMB) return;
    int k = i / D_EMB, j = i % D_EMB;
    float x = T[i];
    __half h = __float2half_rn(x);
    __half l = __float2half_rn(x - __half2float(h));
    g_B2[(size_t)k * D_EMB + j]               = h;
    g_B2[(size_t)(k + D_EMB) * D_EMB + j]     = l;
    g_B2[(size_t)(k + 2 * D_EMB) * D_EMB + j] = h;
}

// ---------------- wmma GEMM: CTA tile 128x256, warp tile 64x64, k-chunk 16 -------
// MODE 0: P   = Bcat @ B2        (M=8192, N=256,  K=768)   B row-major [K,N]
// MODE 1: S   = Acat @ Bcat^T    (M=8192, N=8192, K=768)   B col-major [N,K]
// MODE 2: M1  = gated @ Xh       (M=8192, N=1024, K=8192)  B row-major [K,N]
// MODE 3: out = M1h @ Gh         (M=8192, N=1024, K=1024)  B row-major [K,N]
// Loads: register-staged float4 LDG -> STS, double buffered (R5-proven scheme).
template <int MODE>
__global__ __launch_bounds__(256)
void gemm_wmma3(const float* __restrict__ aux, float* __restrict__ outf) {
    constexpr bool B_COL = (MODE == 1);
    constexpr int K    = (MODE <= 1) ? KCAT : (MODE == 2 ? N_CELLS : D_GENE);
    constexpr int NK   = K / 16;
    constexpr int Ndim = (MODE == 0) ? D_EMB : (MODE == 1 ? N_CELLS : D_GENE);
    constexpr int LDA  = 24;    // A smem pitch (halves): 16 data + 8 pad
    constexpr int LDB  = B_COL ? 24 : 264;  // B pitch: [n][k] 24 | [k][n] 256+8

    const __half* __restrict__ A =
        (MODE == 0) ? g_Bcat : (MODE == 1) ? g_Acat : (MODE == 2) ? g_gated : g_M1h;
    const __half* __restrict__ B =
        (MODE == 0) ? g_B2 : (MODE == 1) ? g_Bcat : (MODE == 2) ? g_Xh : g_Gh;

    __shared__ __align__(16) __half As[2][128 * 24];   // 12288 B
    __shared__ __align__(16) __half Bs[2][6144];       // 24576 B (col: 256x24; row: 16x264)
    __shared__ __align__(16) float  epbuf[8][320];     // 10240 B  => total 47104 B

    const int tid  = threadIdx.x;
    const int lane = tid & 31;
    const int w    = tid >> 5;
    const int wm   = w >> 2;   // 0..1
    const int wn   = w & 3;    // 0..3
    const size_t gm0 = (size_t)blockIdx.y * 128;
    const size_t gn0 = (size_t)blockIdx.x * 256;

    wmma::fragment<wmma::accumulator, 16, 16, 16, float> acc[4][4];
#pragma unroll
    for (int i = 0; i < 4; i++)
#pragma unroll
        for (int j = 0; j < 4; j++) wmma::fill_fragment(acc[i][j], 0.0f);

    // ---- register staging (1 float4 for A, 2 for B) ----
    float4 rA, rB[2];
    const int arow = tid >> 1, ach = tid & 1;          // A: 128 rows x 2 chunks

    auto fetch = [&](int k0) {
        rA = *(const float4*)(A + (gm0 + arow) * (size_t)K + k0 + ach * 8);
        if (B_COL) {
#pragma unroll
            for (int j = 0; j < 2; j++) {
                int idx = tid + j * 256;
                int row = idx >> 1, ch = idx & 1;      // 256 rows x 2 chunks
                rB[j] = *(const float4*)(B + (gn0 + row) * (size_t)K + k0 + ch * 8);
            }
        } else {
#pragma unroll
            for (int j = 0; j < 2; j++) {
                int idx = tid + j * 256;
                int row = idx >> 5, ch = idx & 31;     // 16 rows x 32 chunks
                rB[j] = *(const float4*)(B + (size_t)(k0 + row) * Ndim + gn0 + ch * 8);
            }
        }
    };
    auto store = [&](int buf) {
        *(float4*)(&As[buf][arow * LDA + ach * 8]) = rA;
        if (B_COL) {
#pragma unroll
            for (int j = 0; j < 2; j++) {
                int idx = tid + j * 256;
                int row = idx >> 1, ch = idx & 1;
                *(float4*)(&Bs[buf][row * 24 + ch * 8]) = rB[j];
            }
        } else {
#pragma unroll
            for (int j = 0; j < 2; j++) {
                int idx = tid + j * 256;
                int row = idx >> 5, ch = idx & 31;
                *(float4*)(&Bs[buf][row * 264 + ch * 8]) = rB[j];
            }
        }
    };

    fetch(0);

#pragma unroll 1
    for (int it = 0; it < NK; ++it) {
        const int buf = it & 1;
        store(buf);
        __syncthreads();   // stage visible; reads of `buf` from iter it-2 long done
        if (it + 1 < NK) fetch((it + 1) * 16);

        if constexpr (B_COL) {
            wmma::fragment<wmma::matrix_b, 16, 16, 16, __half, wmma::col_major> b[4];
#pragma unroll
            for (int nt = 0; nt < 4; nt++)
                wmma::load_matrix_sync(b[nt], &Bs[buf][(wn * 64 + nt * 16) * 24], 24);
#pragma unroll
            for (int mt = 0; mt < 4; mt++) {
                wmma::fragment<wmma::matrix_a, 16, 16, 16, __half, wmma::row_major> a;
                wmma::load_matrix_sync(a, &As[buf][(wm * 64 + mt * 16) * LDA], LDA);
#pragma unroll
                for (int nt = 0; nt < 4; nt++)
                    wmma::mma_sync(acc[mt][nt], a, b[nt], acc[mt][nt]);
            }
        } else {
            wmma::fragment<wmma::matrix_b, 16, 16, 16, __half, wmma::row_major> b[4];
#pragma unroll
            for (int nt = 0; nt < 4; nt++)
                wmma::load_matrix_sync(b[nt], &Bs[buf][wn * 64 + nt * 16], 264);
#pragma unroll
            for (int mt = 0; mt < 4; mt++) {
                wmma::fragment<wmma::matrix_a, 16, 16, 16, __half, wmma::row_major> a;
                wmma::load_matrix_sync(a, &As[buf][(wm * 64 + mt * 16) * LDA], LDA);
#pragma unroll
                for (int nt = 0; nt < 4; nt++)
                    wmma::mma_sync(acc[mt][nt], a, b[nt], acc[mt][nt]);
            }
        }
    }

    // ---------------- epilogue (per-warp staging, R1-proven pattern) ----------------
    const int r  = lane >> 1;
    const int cb = (lane & 1) * 8;
#pragma unroll
    for (int mt = 0; mt < 4; mt++) {
        const size_t gr = gm0 + wm * 64 + mt * 16 + r;
#pragma unroll
        for (int nt = 0; nt < 4; nt++) {
            wmma::store_matrix_sync(&epbuf[w][0], acc[mt][nt], 20, wmma::mem_row_major);
            __syncwarp();
            const size_t gc = gn0 + wn * 64 + nt * 16 + cb;
            float v[8];
#pragma unroll
            for (int e = 0; e < 8; e++) v[e] = epbuf[w][r * 20 + cb + e];

            if constexpr (MODE == 0) {
                __half2 hh[4], ll[4];
#pragma unroll
                for (int e = 0; e < 4; e++) {
                    __half h0 = __float2half_rn(v[e * 2]);
                    __half h1 = __float2half_rn(v[e * 2 + 1]);
                    hh[e] = __halves2half2(h0, h1);
                    ll[e] = __halves2half2(
                        __float2half_rn(v[e * 2]     - __half2float(h0)),
                        __float2half_rn(v[e * 2 + 1] - __half2float(h1)));
                }
                size_t base = gr * KCAT + gc;
                *(uint4*)(g_Acat + base)             = *(uint4*)hh;
                *(uint4*)(g_Acat + base + D_EMB)     = *(uint4*)ll;
                *(uint4*)(g_Acat + base + 2 * D_EMB) = *(uint4*)hh;
            } else if constexpr (MODE == 1) {
                const float* prow = aux + gr * (size_t)N_CELLS + gc;
                float4 p0 = __ldcs((const float4*)prow);
                float4 p1 = __ldcs((const float4*)(prow + 4));
                float pv[8] = {p0.x, p0.y, p0.z, p0.w, p1.x, p1.y, p1.z, p1.w};
                __half2 o[4];
#pragma unroll
                for (int e = 0; e < 4; e++) {
                    float s0 = __expf(pv[e * 2]     * -1e-4f) / (1.0f + __expf(-v[e * 2]));
                    float s1 = __expf(pv[e * 2 + 1] * -1e-4f) / (1.0f + __expf(-v[e * 2 + 1]));
                    o[e] = __floats2half2_rn(s0, s1);
                }
                *(uint4*)(g_gated + gr * (size_t)N_CELLS + gc) = *(uint4*)o;
            } else if constexpr (MODE == 2) {
                __half2 o[4];
#pragma unroll
                for (int e = 0; e < 4; e++)
                    o[e] = __floats2half2_rn(v[e * 2], v[e * 2 + 1]);
                *(uint4*)(g_M1h + gr * D_GENE + gc) = *(uint4*)o;
            } else {
                float4 o0 = make_float4(v[0] * (1.0f / 1024.0f), v[1] * (1.0f / 1024.0f),
                                        v[2] * (1.0f / 1024.0f), v[3] * (1.0f / 1024.0f));
                float4 o1 = make_float4(v[4] * (1.0f / 1024.0f), v[5] * (1.0f / 1024.0f),
                                        v[6] * (1.0f / 1024.0f), v[7] * (1.0f / 1024.0f));
                *(float4*)(outf + gr * D_GENE + gc)     = o0;
                *(float4*)(outf + gr * D_GENE + gc + 4) = o1;
            }
            __syncwarp();
        }
    }
}

// ---------------- launch ----------------
extern "C" void kernel_launch(void* const* d_in, const int* in_sizes, int n_in,
                              void* d_out, int out_size) {
    const float* expr = (const float*)d_in[0];
    const float* enc  = (const float*)d_in[1];
    const float* pd   = (const float*)d_in[2];
    const float* T    = (const float*)d_in[3];
    const float* gr   = (const float*)d_in[4];
    float* out = (float*)d_out;

    // conversions (R1 originals)
    k_cvt_expr<<<(N_CELLS * D_GENE) / 256, 256>>>(expr);
    k_cvt_gr<<<(D_GENE * D_GENE) / 256, 256>>>(gr);
    k_cvt_enc<<<(N_CELLS * D_EMB) / 256, 256>>>(enc);
    k_cvt_T<<<(D_EMB * D_EMB) / 256, 256>>>(T);

    // GEMM chain (CTA 128x256; grid.x fastest for L2 reuse of A panels)
    gemm_wmma3<0><<<dim3(D_EMB / 256,  N_CELLS / 128), 256>>>(nullptr, nullptr);
    gemm_wmma3<1><<<dim3(N_CELLS / 256, N_CELLS / 128), 256>>>(pd, nullptr);
    gemm_wmma3<2><<<dim3(D_GENE / 256, N_CELLS / 128), 256>>>(nullptr, nullptr);
    gemm_wmma3<3><<<dim3(D_GENE / 256, N_CELLS / 128), 256>>>(nullptr, out);
}